// round 12
// baseline (speedup 1.0000x reference)
#include <cuda_runtime.h>
#include <cuda_fp16.h>
#include <cstdint>

// ---------------------------------------------------------------------------
// Problem constants
// ---------------------------------------------------------------------------
#define B_  32
#define D_  3
#define T_  16384
#define S_  128
#define L_  16
#define H_  512
#define C_  10
#define TP  16369          // T - L + 1 valid positions
#define SHN 48             // D*L = K (3 k-steps of 16)

#define NT      256        // positions per block tile (two 128-col MMA halves)
#define NTILES  (B_ * (T_ / NT))   // 2048
#define THR     256
#define GRID    293        // <= 296 co-resident (2/SM) -> spin-wait is safe
#define XT_W    (NT + L_)  // 272 elements per x row in tile
#define LD4     ((D_ * XT_W) / 4)  // 204 float4 loads per tile

#define INF_F __int_as_float(0x7F800000)

// monotonic arrival counter (zero-init; grows by GRID per launch/replay)
__device__ unsigned long long g_ctr;

// ---------------------------------------------------------------------------
// D(16x8) += A(16x16,row) * B(16x8,col)   f16 x f16 -> f32
__device__ __forceinline__ void mma16(float* d, uint32_t a0, uint32_t a1,
                                      uint32_t a2, uint32_t a3,
                                      uint32_t b0, uint32_t b1) {
    asm volatile(
        "mma.sync.aligned.m16n8k16.row.col.f32.f16.f16.f32 "
        "{%0,%1,%2,%3}, {%4,%5,%6,%7}, {%8,%9}, {%0,%1,%2,%3};"
        : "+f"(d[0]), "+f"(d[1]), "+f"(d[2]), "+f"(d[3])
        : "r"(a0), "r"(a1), "r"(a2), "r"(a3), "r"(b0), "r"(b1));
}

__device__ __forceinline__ uint32_t packh2(float lo, float hi) {
    __half2 h = __floats2half2_rn(lo, hi);
    return *reinterpret_cast<uint32_t*>(&h);
}

// tile float4 load (tid < LD4), zero-padded past T
__device__ __forceinline__ float4 load_tile_f4(const float* __restrict__ x,
                                               int tile, int tid) {
    const int b     = tile >> 6;                 // 64 tiles / batch
    const int tbase = (tile & 63) * NT;
    const int d     = tid / (XT_W / 4);          // XT_W/4 = 68
    const int j     = (tid % (XT_W / 4)) * 4;
    const int g     = tbase + j;
    const float* xr = x + (size_t)b * D_ * T_ + d * T_;
    float4 v;
    if (g + 3 < T_) {
        v = *reinterpret_cast<const float4*>(xr + g);
    } else {
        v.x = (g     < T_) ? xr[g]     : 0.f;
        v.y = (g + 1 < T_) ? xr[g + 1] : 0.f;
        v.z = (g + 2 < T_) ? xr[g + 2] : 0.f;
        v.w = (g + 3 < T_) ? xr[g + 3] : 0.f;
    }
    return v;
}

// ---------------------------------------------------------------------------
// MLP tail: one block handles one batch. __noinline__ to shield main-loop regs.
// ---------------------------------------------------------------------------
__device__ __noinline__ void mlp_tail(
    int b, const float* __restrict__ dist,
    const float* __restrict__ W1, const float* __restrict__ b1,
    const float* __restrict__ W2, const float* __restrict__ b2,
    float* __restrict__ out_cls, float* hs)
{
    const int tid  = threadIdx.x;    // 256 = 8 warps
    const int wid  = tid >> 5;
    const int lane = tid & 31;

    const float4 d4 = reinterpret_cast<const float4*>(dist + b * S_)[lane];

    // Layer 1: warp w -> neurons [w*64, w*64+64), 4 at a time (ILP shfl chains)
    for (int i = 0; i < 16; ++i) {
        float acc[4];
        #pragma unroll
        for (int j = 0; j < 4; ++j) {
            const int h = wid * 64 + i * 4 + j;
            const float4 w4 =
                reinterpret_cast<const float4*>(W1 + h * S_)[lane];
            float a = d4.x * w4.x;
            a = fmaf(d4.y, w4.y, a);
            a = fmaf(d4.z, w4.z, a);
            a = fmaf(d4.w, w4.w, a);
            acc[j] = a;
        }
        #pragma unroll
        for (int off = 16; off > 0; off >>= 1)
            #pragma unroll
            for (int j = 0; j < 4; ++j)
                acc[j] += __shfl_xor_sync(0xffffffffu, acc[j], off);
        #pragma unroll
        for (int j = 0; j < 4; ++j)
            if (lane == j) {
                const int h = wid * 64 + i * 4 + j;
                hs[h] = fmaxf(acc[j] + b1[h], 0.f);
            }
    }
    __syncthreads();

    // Layer 2: classes round-robin over 8 warps (warps 0,1 take two)
    for (int c = wid; c < C_; c += 8) {
        const float4* w4p = reinterpret_cast<const float4*>(W2 + c * H_);
        const float4* h4p = reinterpret_cast<const float4*>(hs);
        float acc = 0.f;
        #pragma unroll
        for (int jj = 0; jj < 4; ++jj) {
            const float4 w4 = w4p[lane + jj * 32];
            const float4 h4 = h4p[lane + jj * 32];
            acc = fmaf(w4.x, h4.x, acc);
            acc = fmaf(w4.y, h4.y, acc);
            acc = fmaf(w4.z, h4.z, acc);
            acc = fmaf(w4.w, h4.w, acc);
        }
        #pragma unroll
        for (int off = 16; off > 0; off >>= 1)
            acc += __shfl_xor_sync(0xffffffffu, acc, off);
        if (lane == 0) out_cls[b * C_ + c] = acc + b2[c];
    }
}

// ---------------------------------------------------------------------------
// Kernel: persistent fp16-MMA shapelet distance + arrival-rank MLP tail
// ---------------------------------------------------------------------------
__global__ __launch_bounds__(THR, 2) void dist_kernel(
    const float* __restrict__ x,
    const float* __restrict__ shg,
    const float* __restrict__ W1,
    const float* __restrict__ b1,
    const float* __restrict__ W2,
    const float* __restrict__ b2,
    float* __restrict__ out_dist,
    float* __restrict__ out_cls)
{
    // NOTE: explicit 16B alignment — these are accessed via float4/uint32
    // reinterpret casts; shared-var layout gives only element alignment.
    __shared__ __align__(16) float  xs[D_ * XT_W];   // raw fp32 (wsq; reused as hs)
    __shared__ __align__(16) __half hA[D_ * XT_W];   // hA[i] = f16(x[i])
    __shared__ __align__(16) __half hB[D_ * XT_W];   // hB[i] = f16(x[i+1])
    __shared__ __align__(16) float  swsq[NT];
    __shared__ float  sssq[S_];
    __shared__ int    sdmin[S_];
    __shared__ unsigned long long s_old;

    const int tid  = threadIdx.x;
    const int wid  = tid >> 5;
    const int lane = tid & 31;
    const int q    = lane >> 2;
    const int r    = lane & 3;

    const int mbase = (wid & 3) * 32;
    const int nbase = (wid >> 2) * 64;

    // --- one-time: exact shapelet norms; A fragments -> regs ---
    if (tid < S_) {
        const float* srow = shg + tid * SHN;
        float ssq = 0.f;
        #pragma unroll
        for (int k = 0; k < SHN; ++k) ssq = fmaf(srow[k], srow[k], ssq);
        sssq[tid] = ssq;
        sdmin[tid] = 0x7F800000;
    }

    uint32_t afr[3][2][4];
    #pragma unroll
    for (int ks = 0; ks < 3; ++ks) {
        #pragma unroll
        for (int mt = 0; mt < 2; ++mt) {
            const int r0 = mbase + mt * 16 + q;
            const int r1 = r0 + 8;
            const int k0 = ks * 16 + 2 * r;
            const float* p0 = shg + r0 * SHN + k0;
            const float* p1 = shg + r1 * SHN + k0;
            afr[ks][mt][0] = packh2(-2.f * p0[0], -2.f * p0[1]);
            afr[ks][mt][1] = packh2(-2.f * p1[0], -2.f * p1[1]);
            afr[ks][mt][2] = packh2(-2.f * p0[8], -2.f * p0[9]);
            afr[ks][mt][3] = packh2(-2.f * p1[8], -2.f * p1[9]);
        }
    }
    __syncthreads();

    const uint32_t* hA32 = reinterpret_cast<const uint32_t*>(hA);
    const uint32_t* hB32 = reinterpret_cast<const uint32_t*>(hB);
    const uint32_t* hw = (q & 1) ? hB32 : hA32;
    const int lane_off = q + 2 * r - (q & 1);

    // ---- prologue: prefetch first tile ----
    float4 v = make_float4(0.f, 0.f, 0.f, 0.f);
    if (blockIdx.x < NTILES && tid < LD4)
        v = load_tile_f4(x, blockIdx.x, tid);

    for (int tile = blockIdx.x; tile < NTILES; tile += GRID) {
        const int b = tile >> 6;

        // ---- STS phase: commit prefetched regs to smem ----
        if (tid < LD4) {
            const int d = tid / (XT_W / 4);
            const int j = (tid % (XT_W / 4)) * 4;
            *reinterpret_cast<float4*>(&xs[d * XT_W + j]) = v;
            const int hi = d * XT_W + j;
            *reinterpret_cast<uint32_t*>(&hA[hi])     = packh2(v.x, v.y);
            *reinterpret_cast<uint32_t*>(&hA[hi + 2]) = packh2(v.z, v.w);
            if (j > 0) hB[hi - 1] = __float2half(v.x);
            hB[hi    ] = __float2half(v.y);
            hB[hi + 1] = __float2half(v.z);
            hB[hi + 2] = __float2half(v.w);
        }
        __syncthreads();

        // ---- prefetch next tile (latency hidden behind wsq + MMA) ----
        {
            const int tnext = tile + GRID;
            if (tnext < NTILES && tid < LD4)
                v = load_tile_f4(x, tnext, tid);
        }

        // ---- wsq: one position per thread ----
        {
            const int tbase = (tile & 63) * NT;
            float w0 = 0.f, w1 = 0.f, w2 = 0.f;
            #pragma unroll
            for (int l = 0; l < L_; ++l) {
                const float v0 = xs[0 * XT_W + tid + l];
                const float v1 = xs[1 * XT_W + tid + l];
                const float v2 = xs[2 * XT_W + tid + l];
                w0 = fmaf(v0, v0, w0);
                w1 = fmaf(v1, v1, w1);
                w2 = fmaf(v2, v2, w2);
            }
            swsq[tid] = (tbase + tid < TP) ? (w0 + w1 + w2) : INF_F;
        }
        __syncthreads();

        // ---- MMA + epilogue: two N-halves ----
        float rmin[2][2];
        #pragma unroll
        for (int mt = 0; mt < 2; ++mt)
            #pragma unroll
            for (int h = 0; h < 2; ++h) rmin[mt][h] = INF_F;

        #pragma unroll
        for (int half = 0; half < 2; ++half) {
            const int nbh = half * 128 + nbase;

            float acc[2][8][4];
            #pragma unroll
            for (int mt = 0; mt < 2; ++mt)
                #pragma unroll
                for (int nt = 0; nt < 8; ++nt)
                    #pragma unroll
                    for (int e = 0; e < 4; ++e) acc[mt][nt][e] = 0.f;

            #pragma unroll
            for (int ks = 0; ks < 3; ++ks) {
                const int base = (ks * XT_W + nbh + lane_off) >> 1;
                #pragma unroll
                for (int nt = 0; nt < 8; ++nt) {
                    const uint32_t b0 = hw[base + nt * 4];
                    const uint32_t b1 = hw[base + nt * 4 + 4];
                    mma16(acc[0][nt], afr[ks][0][0], afr[ks][0][1],
                                      afr[ks][0][2], afr[ks][0][3], b0, b1);
                    mma16(acc[1][nt], afr[ks][1][0], afr[ks][1][1],
                                      afr[ks][1][2], afr[ks][1][3], b0, b1);
                }
            }

            float wq[8][2];
            #pragma unroll
            for (int nt = 0; nt < 8; ++nt) {
                wq[nt][0] = swsq[nbh + nt * 8 + r * 2    ];
                wq[nt][1] = swsq[nbh + nt * 8 + r * 2 + 1];
            }
            #pragma unroll
            for (int mt = 0; mt < 2; ++mt)
                #pragma unroll
                for (int h = 0; h < 2; ++h) {
                    float m = rmin[mt][h];
                    #pragma unroll
                    for (int nt = 0; nt < 8; ++nt) {
                        m = fminf(m, acc[mt][nt][h * 2    ] + wq[nt][0]);
                        m = fminf(m, acc[mt][nt][h * 2 + 1] + wq[nt][1]);
                    }
                    rmin[mt][h] = m;
                }
        }

        // ---- quad shfl + smem atomic min ----
        #pragma unroll
        for (int mt = 0; mt < 2; ++mt)
            #pragma unroll
            for (int h = 0; h < 2; ++h) {
                float mv = rmin[mt][h];
                mv = fminf(mv, __shfl_xor_sync(0xffffffffu, mv, 1));
                mv = fminf(mv, __shfl_xor_sync(0xffffffffu, mv, 2));
                rmin[mt][h] = mv;
            }
        if (r == 0) {
            #pragma unroll
            for (int mt = 0; mt < 2; ++mt)
                #pragma unroll
                for (int h = 0; h < 2; ++h) {
                    const int row = mbase + mt * 16 + h * 8 + q;
                    const float vv = rmin[mt][h] + sssq[row];
                    atomicMin(&sdmin[row], __float_as_int(vv));
                }
        }
        __syncthreads();

        // ---- fold into global; reset own slot ----
        if (tid < S_) {
            const int dv = sdmin[tid];
            atomicMin(reinterpret_cast<int*>(out_dist) + b * S_ + tid, dv);
            sdmin[tid] = 0x7F800000;
        }
    }

    // ================= arrival-rank MLP tail ================================
    __threadfence();                       // distances globally visible
    if (tid == 0) s_old = atomicAdd(&g_ctr, 1ULL);
    __syncthreads();
    const unsigned long long old = s_old;
    const int pos = (int)(old % (unsigned long long)GRID);
    if (pos < GRID - B_) return;           // only last 32 arrivals continue
    const int batch = pos - (GRID - B_);

    if (tid == 0) {
        const unsigned long long target = old - (unsigned long long)pos + GRID;
        while (*(volatile unsigned long long*)&g_ctr < target)
            __nanosleep(64);
    }
    __syncthreads();
    __threadfence();                       // see all blocks' distance writes

    mlp_tail(batch, out_dist, W1, b1, W2, b2, out_cls, xs);
}

// ---------------------------------------------------------------------------
extern "C" void kernel_launch(void* const* d_in, const int* in_sizes, int n_in,
                              void* d_out, int out_size)
{
    const float* x  = (const float*)d_in[0];
    const float* sh = (const float*)d_in[1];
    const float* W1 = (const float*)d_in[2];
    const float* b1 = (const float*)d_in[3];
    const float* W2 = (const float*)d_in[4];
    const float* b2 = (const float*)d_in[5];

    float* out_dist = (float*)d_out;
    float* out_cls  = (float*)d_out + B_ * S_;

    // distances -> huge positive sentinel (0x7f7f7f7f ~ 3.39e38)
    cudaMemsetAsync(out_dist, 0x7f, B_ * S_ * sizeof(float), 0);

    dist_kernel<<<GRID, THR>>>(x, sh, W1, b1, W2, b2, out_dist, out_cls);
}

// round 13
// speedup vs baseline: 1.1394x; 1.1394x over previous
#include <cuda_runtime.h>
#include <cuda_fp16.h>
#include <cstdint>

// ---------------------------------------------------------------------------
// Problem constants
// ---------------------------------------------------------------------------
#define B_  32
#define D_  3
#define T_  16384
#define S_  128
#define L_  16
#define H_  512
#define C_  10
#define TP  16369          // T - L + 1 valid positions
#define SHN 48             // D*L = K (3 k-steps of 16)

#define NT      128        // positions per block tile (GEMM N-tile)
#define NTILES  (B_ * (T_ / NT))   // 4096
#define THR     256
#define GRID    296        // 2 blocks / SM
#define XT_W    (NT + L_)  // 144 elements per x row in tile
#define XT_N    (D_ * XT_W)        // 432 floats per tile
#define LD4     (XT_N / 4)         // 108 cp.async per tile

#define INF_F __int_as_float(0x7F800000)

// ---------------------------------------------------------------------------
// D(16x8) += A(16x16,row) * B(16x8,col)   f16 x f16 -> f32
__device__ __forceinline__ void mma16(float* d, uint32_t a0, uint32_t a1,
                                      uint32_t a2, uint32_t a3,
                                      uint32_t b0, uint32_t b1) {
    asm volatile(
        "mma.sync.aligned.m16n8k16.row.col.f32.f16.f16.f32 "
        "{%0,%1,%2,%3}, {%4,%5,%6,%7}, {%8,%9}, {%0,%1,%2,%3};"
        : "+f"(d[0]), "+f"(d[1]), "+f"(d[2]), "+f"(d[3])
        : "r"(a0), "r"(a1), "r"(a2), "r"(a3), "r"(b0), "r"(b1));
}

__device__ __forceinline__ uint32_t packh2(float lo, float hi) {
    __half2 h = __floats2half2_rn(lo, hi);
    return *reinterpret_cast<uint32_t*>(&h);
}

__device__ __forceinline__ void cp_async16(uint32_t dst_smem, const void* src,
                                           int src_bytes) {
    asm volatile("cp.async.ca.shared.global [%0], [%1], 16, %2;"
                 :: "r"(dst_smem), "l"(src), "r"(src_bytes));
}
#define CP_COMMIT() asm volatile("cp.async.commit_group;" ::: "memory")
#define CP_WAIT1()  asm volatile("cp.async.wait_group 1;"  ::: "memory")

// ---------------------------------------------------------------------------
// Kernel 1: persistent fp16-MMA shapelet distance, cp.async double-buffered
// ---------------------------------------------------------------------------
__global__ __launch_bounds__(THR, 2) void dist_kernel(
    const float* __restrict__ x,
    const float* __restrict__ shg,
    float* __restrict__ out_dist)
{
    __shared__ __align__(16) float  xs[2][XT_N];   // raw fp32, double-buffered
    __shared__ __align__(16) __half hA[XT_N];      // hA[i] = f16(x[i])
    __shared__ __align__(16) __half hB[XT_N];      // hB[i] = f16(x[i+1] in-row)
    __shared__ __align__(16) float  swsq[NT];
    __shared__ float  sssq[S_];
    __shared__ int    sdmin[S_];

    const int tid  = threadIdx.x;
    const int wid  = tid >> 5;
    const int lane = tid & 31;
    const int q    = lane >> 2;      // groupID
    const int r    = lane & 3;       // threadID_in_group

    const int mbase = (wid & 3) * 32;       // warp's 32 M-rows
    const int nbase = (wid >> 2) * 64;      // warp's 64 N-cols

    // --- one-time: exact fp32 shapelet squared norms; A fragments -> regs ---
    if (tid < S_) {
        const float* srow = shg + tid * SHN;
        float ssq = 0.f;
        #pragma unroll
        for (int k = 0; k < SHN; ++k) ssq = fmaf(srow[k], srow[k], ssq);
        sssq[tid] = ssq;
        sdmin[tid] = 0x7F800000;
    }

    // A fragments: afr[ks][mt][4]; tile-invariant
    uint32_t afr[3][2][4];
    #pragma unroll
    for (int ks = 0; ks < 3; ++ks) {
        #pragma unroll
        for (int mt = 0; mt < 2; ++mt) {
            const int r0 = mbase + mt * 16 + q;
            const int r1 = r0 + 8;
            const int k0 = ks * 16 + 2 * r;
            const float* p0 = shg + r0 * SHN + k0;
            const float* p1 = shg + r1 * SHN + k0;
            afr[ks][mt][0] = packh2(-2.f * p0[0], -2.f * p0[1]);
            afr[ks][mt][1] = packh2(-2.f * p1[0], -2.f * p1[1]);
            afr[ks][mt][2] = packh2(-2.f * p0[8], -2.f * p0[9]);
            afr[ks][mt][3] = packh2(-2.f * p1[8], -2.f * p1[9]);
        }
    }

    const uint32_t* hA32 = reinterpret_cast<const uint32_t*>(hA);
    const uint32_t* hB32 = reinterpret_cast<const uint32_t*>(hB);
    const uint32_t* hw = (q & 1) ? hB32 : hA32;
    const int lane_off = q + 2 * r - (q & 1);

    // cp.async issue: 108 threads, one 16B op each; tail zero-filled via src_size
    auto issue_cp = [&](int tile, int buf) {
        if (tid < LD4) {
            const int b     = tile >> 7;          // 128 tiles / batch
            const int tbase = (tile & 127) * NT;
            const int d     = tid / (XT_W / 4);   // XT_W/4 = 36
            const int j     = (tid % (XT_W / 4)) * 4;
            const int g     = tbase + j;
            const float* xr = x + (size_t)b * D_ * T_ + d * T_;
            int bytes = (T_ - g) * 4;
            bytes = bytes > 16 ? 16 : (bytes < 0 ? 0 : bytes);
            const float* src = xr + (g <= T_ - 4 ? g : T_ - 4);
            cp_async16((uint32_t)__cvta_generic_to_shared(&xs[buf][d * XT_W + j]),
                       src, bytes);
        }
    };

    // ---- prologue: start first tile ----
    if (blockIdx.x < NTILES) issue_cp(blockIdx.x, 0);
    CP_COMMIT();
    __syncthreads();   // sdmin/sssq init visible

    int buf = 0;
    for (int tile = blockIdx.x; tile < NTILES; tile += GRID) {
        const int b     = tile >> 7;
        const int tbase = (tile & 127) * NT;

        // ---- kick next tile's loads, then wait for current buffer ----
        const int tnext = tile + GRID;
        if (tnext < NTILES) issue_cp(tnext, buf ^ 1);
        CP_COMMIT();
        CP_WAIT1();          // current tile's group (and older) complete
        __syncthreads();

        const float* xb = xs[buf];

        // ---- convert fp32 -> fp16 copies (2 elems/thread) ----
        #pragma unroll
        for (int i = tid; i < XT_N; i += THR) {
            const float cur = xb[i];
            hA[i] = __float2half(cur);
            const int col = i - (i / XT_W) * XT_W;
            hB[i] = (col + 1 < XT_W) ? __float2half(xb[i + 1]) : __half(0.f);
        }

        // ---- wsq: one position per thread (tid < 128) ----
        if (tid < NT) {
            float w0 = 0.f, w1 = 0.f, w2 = 0.f;
            #pragma unroll
            for (int l = 0; l < L_; ++l) {
                const float v0 = xb[0 * XT_W + tid + l];
                const float v1 = xb[1 * XT_W + tid + l];
                const float v2 = xb[2 * XT_W + tid + l];
                w0 = fmaf(v0, v0, w0);
                w1 = fmaf(v1, v1, w1);
                w2 = fmaf(v2, v2, w2);
            }
            swsq[tid] = (tbase + tid < TP) ? (w0 + w1 + w2) : INF_F;
        }
        __syncthreads();

        // ---- MMA: warp tile 32M x 64N, K=48 (3 k-steps) ----
        float acc[2][8][4];
        #pragma unroll
        for (int mt = 0; mt < 2; ++mt)
            #pragma unroll
            for (int nt = 0; nt < 8; ++nt)
                #pragma unroll
                for (int e = 0; e < 4; ++e) acc[mt][nt][e] = 0.f;

        #pragma unroll
        for (int ks = 0; ks < 3; ++ks) {
            const int base = (ks * XT_W + nbase + lane_off) >> 1;
            #pragma unroll
            for (int nt = 0; nt < 8; ++nt) {
                const uint32_t b0 = hw[base + nt * 4];
                const uint32_t b1 = hw[base + nt * 4 + 4];
                mma16(acc[0][nt], afr[ks][0][0], afr[ks][0][1],
                                  afr[ks][0][2], afr[ks][0][3], b0, b1);
                mma16(acc[1][nt], afr[ks][1][0], afr[ks][1][1],
                                  afr[ks][1][2], afr[ks][1][3], b0, b1);
            }
        }

        // ---- epilogue: dist = min_n(acc + wsq[n]) ----
        float wq[8][2];
        #pragma unroll
        for (int nt = 0; nt < 8; ++nt) {
            wq[nt][0] = swsq[nbase + nt * 8 + r * 2    ];
            wq[nt][1] = swsq[nbase + nt * 8 + r * 2 + 1];
        }
        float rmin[2][2];
        #pragma unroll
        for (int mt = 0; mt < 2; ++mt)
            #pragma unroll
            for (int h = 0; h < 2; ++h) {
                float m = INF_F;
                #pragma unroll
                for (int nt = 0; nt < 8; ++nt) {
                    m = fminf(m, acc[mt][nt][h * 2    ] + wq[nt][0]);
                    m = fminf(m, acc[mt][nt][h * 2 + 1] + wq[nt][1]);
                }
                rmin[mt][h] = m;
            }
        #pragma unroll
        for (int mt = 0; mt < 2; ++mt)
            #pragma unroll
            for (int h = 0; h < 2; ++h) {
                float v = rmin[mt][h];
                v = fminf(v, __shfl_xor_sync(0xffffffffu, v, 1));
                v = fminf(v, __shfl_xor_sync(0xffffffffu, v, 2));
                rmin[mt][h] = v;
            }
        if (r == 0) {
            #pragma unroll
            for (int mt = 0; mt < 2; ++mt)
                #pragma unroll
                for (int h = 0; h < 2; ++h) {
                    const int row = mbase + mt * 16 + h * 8 + q;
                    const float v = rmin[mt][h] + sssq[row];
                    atomicMin(&sdmin[row], __float_as_int(v));
                }
        }
        __syncthreads();

        // ---- fold into global; reset own slot ----
        if (tid < S_) {
            const int v = sdmin[tid];
            atomicMin(reinterpret_cast<int*>(out_dist) + b * S_ + tid, v);
            sdmin[tid] = 0x7F800000;
        }
        buf ^= 1;
    }
}

// ---------------------------------------------------------------------------
// Kernel 2: MLP — coalesced rows, 4-way ILP reductions
// ---------------------------------------------------------------------------
__global__ __launch_bounds__(512) void mlp_kernel(
    const float* __restrict__ dist,
    const float* __restrict__ W1,
    const float* __restrict__ b1,
    const float* __restrict__ W2,
    const float* __restrict__ b2,
    float* __restrict__ out_cls)
{
    __shared__ __align__(16) float hs[H_];
    const int b    = blockIdx.x;
    const int tid  = threadIdx.x;    // 512 threads = 16 warps
    const int warp = tid >> 5;
    const int lane = tid & 31;

    const float4 d4 = reinterpret_cast<const float4*>(dist + b * S_)[lane];

    // Layer 1: warp w -> neurons [w*32, w*32+32), 4 at a time (ILP shfls)
    #pragma unroll
    for (int i = 0; i < 8; ++i) {
        float acc[4];
        #pragma unroll
        for (int j = 0; j < 4; ++j) {
            const int h = warp * 32 + i * 4 + j;
            const float4 w4 =
                reinterpret_cast<const float4*>(W1 + h * S_)[lane];
            float a = d4.x * w4.x;
            a = fmaf(d4.y, w4.y, a);
            a = fmaf(d4.z, w4.z, a);
            a = fmaf(d4.w, w4.w, a);
            acc[j] = a;
        }
        #pragma unroll
        for (int off = 16; off > 0; off >>= 1)
            #pragma unroll
            for (int j = 0; j < 4; ++j)
                acc[j] += __shfl_xor_sync(0xffffffffu, acc[j], off);
        #pragma unroll
        for (int j = 0; j < 4; ++j)
            if (lane == j) {
                const int h = warp * 32 + i * 4 + j;
                hs[h] = fmaxf(acc[j] + b1[h], 0.f);
            }
    }
    __syncthreads();

    // Layer 2: warp w (< 10) computes class w
    if (warp < C_) {
        const float4* w4p = reinterpret_cast<const float4*>(W2 + warp * H_);
        const float4* h4p = reinterpret_cast<const float4*>(hs);
        float acc = 0.f;
        #pragma unroll
        for (int j = 0; j < H_ / (32 * 4); ++j) {
            const float4 w4 = w4p[lane + j * 32];
            const float4 h4 = h4p[lane + j * 32];
            acc = fmaf(w4.x, h4.x, acc);
            acc = fmaf(w4.y, h4.y, acc);
            acc = fmaf(w4.z, h4.z, acc);
            acc = fmaf(w4.w, h4.w, acc);
        }
        #pragma unroll
        for (int off = 16; off > 0; off >>= 1)
            acc += __shfl_xor_sync(0xffffffffu, acc, off);
        if (lane == 0) out_cls[b * C_ + warp] = acc + b2[warp];
    }
}

// ---------------------------------------------------------------------------
extern "C" void kernel_launch(void* const* d_in, const int* in_sizes, int n_in,
                              void* d_out, int out_size)
{
    const float* x  = (const float*)d_in[0];
    const float* sh = (const float*)d_in[1];
    const float* W1 = (const float*)d_in[2];
    const float* b1 = (const float*)d_in[3];
    const float* W2 = (const float*)d_in[4];
    const float* b2 = (const float*)d_in[5];

    float* out_dist = (float*)d_out;
    float* out_cls  = (float*)d_out + B_ * S_;

    // init distances to a huge positive sentinel (0x7f7f7f7f ~ 3.39e38)
    cudaMemsetAsync(out_dist, 0x7f, B_ * S_ * sizeof(float), 0);

    dist_kernel<<<GRID, THR>>>(x, sh, out_dist);
    mlp_kernel<<<B_, 512>>>(out_dist, W1, b1, W2, b2, out_cls);
}

// round 14
// speedup vs baseline: 1.1420x; 1.0023x over previous
#include <cuda_runtime.h>
#include <cuda_fp16.h>
#include <cstdint>

// ---------------------------------------------------------------------------
// Problem constants
// ---------------------------------------------------------------------------
#define B_  32
#define D_  3
#define T_  16384
#define S_  128
#define L_  16
#define H_  512
#define C_  10
#define TP  16369          // T - L + 1 valid positions
#define SHN 48             // D*L = K (3 k-steps of 16)

#define NT      64         // positions per block tile (GEMM N-tile)
#define TPB     (T_ / NT)          // 256 tiles per batch
#define NTILES  (B_ * TPB)         // 8192
#define THR     128        // 4 warps per block
#define GRID    592        // 4 blocks/SM x 148 SMs = one exact wave
#define XT_W    (NT + L_)  // 80 elements per x row in tile
#define LD4     ((D_ * XT_W) / 4)  // 60 float4 loads per tile

#define INF_F __int_as_float(0x7F800000)

// ---------------------------------------------------------------------------
// D(16x8) += A(16x16,row) * B(16x8,col)   f16 x f16 -> f32
__device__ __forceinline__ void mma16(float* d, uint32_t a0, uint32_t a1,
                                      uint32_t a2, uint32_t a3,
                                      uint32_t b0, uint32_t b1) {
    asm volatile(
        "mma.sync.aligned.m16n8k16.row.col.f32.f16.f16.f32 "
        "{%0,%1,%2,%3}, {%4,%5,%6,%7}, {%8,%9}, {%0,%1,%2,%3};"
        : "+f"(d[0]), "+f"(d[1]), "+f"(d[2]), "+f"(d[3])
        : "r"(a0), "r"(a1), "r"(a2), "r"(a3), "r"(b0), "r"(b1));
}

__device__ __forceinline__ uint32_t packh2(float lo, float hi) {
    __half2 h = __floats2half2_rn(lo, hi);
    return *reinterpret_cast<uint32_t*>(&h);
}

// ---------------------------------------------------------------------------
// Kernel 1: persistent fp16-MMA shapelet distance
//   4 warps/block, 4 blocks/SM -> decoupled barrier domains
// ---------------------------------------------------------------------------
__global__ __launch_bounds__(THR, 4) void dist_kernel(
    const float* __restrict__ x,
    const float* __restrict__ shg,
    float* __restrict__ out_dist)
{
    __shared__ __align__(16) float  xs[D_ * XT_W];   // raw fp32 (exact wsq)
    __shared__ __align__(16) __half hA[D_ * XT_W];   // hA[i] = f16(x[i])
    __shared__ __align__(16) __half hB[D_ * XT_W];   // hB[i] = f16(x[i+1] in-row)
    __shared__ __align__(16) float  swsq[NT];
    __shared__ float  sssq[S_];
    __shared__ int    sdmin[S_];

    const int tid  = threadIdx.x;
    const int wid  = tid >> 5;       // 0..3
    const int lane = tid & 31;
    const int q    = lane >> 2;      // groupID
    const int r    = lane & 3;       // threadID_in_group

    const int mbase = wid * 32;      // warp's 32 M-rows; all warps share N

    // --- one-time: exact fp32 shapelet squared norms; A fragments -> regs ---
    {
        const float* srow = shg + tid * SHN;         // tid < 128 == S_
        float ssq = 0.f;
        #pragma unroll
        for (int k = 0; k < SHN; ++k) ssq = fmaf(srow[k], srow[k], ssq);
        sssq[tid] = ssq;
        sdmin[tid] = 0x7F800000;
    }

    // A fragments: afr[ks][mt][4]; tile-invariant
    uint32_t afr[3][2][4];
    #pragma unroll
    for (int ks = 0; ks < 3; ++ks) {
        #pragma unroll
        for (int mt = 0; mt < 2; ++mt) {
            const int r0 = mbase + mt * 16 + q;
            const int r1 = r0 + 8;
            const int k0 = ks * 16 + 2 * r;
            const float* p0 = shg + r0 * SHN + k0;
            const float* p1 = shg + r1 * SHN + k0;
            afr[ks][mt][0] = packh2(-2.f * p0[0], -2.f * p0[1]);
            afr[ks][mt][1] = packh2(-2.f * p1[0], -2.f * p1[1]);
            afr[ks][mt][2] = packh2(-2.f * p0[8], -2.f * p0[9]);
            afr[ks][mt][3] = packh2(-2.f * p1[8], -2.f * p1[9]);
        }
    }
    __syncthreads();

    const uint32_t* hA32 = reinterpret_cast<const uint32_t*>(hA);
    const uint32_t* hB32 = reinterpret_cast<const uint32_t*>(hB);
    const uint32_t* hw = (q & 1) ? hB32 : hA32;
    const int lane_off = q + 2 * r - (q & 1);

    for (int tile = blockIdx.x; tile < NTILES; tile += GRID) {
        const int b     = tile >> 8;                  // TPB = 256
        const int tbase = (tile & (TPB - 1)) * NT;
        const float* xb = x + (size_t)b * D_ * T_;

        // ---- phase 1: load x tile (fp32 + two fp16 copies), 60 float4 ----
        if (tid < LD4) {
            const int d = tid / (XT_W / 4);           // XT_W/4 = 20
            const int j = (tid % (XT_W / 4)) * 4;
            const int g = tbase + j;
            float4 v;
            if (g + 3 < T_) {
                v = *reinterpret_cast<const float4*>(xb + d * T_ + g);
            } else {
                v.x = (g     < T_) ? xb[d*T_ + g]     : 0.f;
                v.y = (g + 1 < T_) ? xb[d*T_ + g + 1] : 0.f;
                v.z = (g + 2 < T_) ? xb[d*T_ + g + 2] : 0.f;
                v.w = (g + 3 < T_) ? xb[d*T_ + g + 3] : 0.f;
            }
            *reinterpret_cast<float4*>(&xs[d * XT_W + j]) = v;
            const int hi = d * XT_W + j;
            *reinterpret_cast<uint32_t*>(&hA[hi])     = packh2(v.x, v.y);
            *reinterpret_cast<uint32_t*>(&hA[hi + 2]) = packh2(v.z, v.w);
            if (j > 0) hB[hi - 1] = __float2half(v.x);
            hB[hi    ] = __float2half(v.y);
            hB[hi + 1] = __float2half(v.z);
            hB[hi + 2] = __float2half(v.w);
        }
        __syncthreads();

        // ---- phase 2: wsq, one position per thread (tid < 64) ----
        if (tid < NT) {
            float w0 = 0.f, w1 = 0.f, w2 = 0.f;
            #pragma unroll
            for (int l = 0; l < L_; ++l) {
                const float v0 = xs[0 * XT_W + tid + l];
                const float v1 = xs[1 * XT_W + tid + l];
                const float v2 = xs[2 * XT_W + tid + l];
                w0 = fmaf(v0, v0, w0);
                w1 = fmaf(v1, v1, w1);
                w2 = fmaf(v2, v2, w2);
            }
            swsq[tid] = (tbase + tid < TP) ? (w0 + w1 + w2) : INF_F;
        }

        // ---- phase 3: MMA, warp tile 32M x 64N, K=48 (3 k-steps) ----
        float acc[2][8][4];
        #pragma unroll
        for (int mt = 0; mt < 2; ++mt)
            #pragma unroll
            for (int nt = 0; nt < 8; ++nt)
                #pragma unroll
                for (int e = 0; e < 4; ++e) acc[mt][nt][e] = 0.f;

        #pragma unroll
        for (int ks = 0; ks < 3; ++ks) {
            const int base = (ks * XT_W + lane_off) >> 1;
            #pragma unroll
            for (int nt = 0; nt < 8; ++nt) {
                const uint32_t b0 = hw[base + nt * 4];
                const uint32_t b1 = hw[base + nt * 4 + 4];
                mma16(acc[0][nt], afr[ks][0][0], afr[ks][0][1],
                                  afr[ks][0][2], afr[ks][0][3], b0, b1);
                mma16(acc[1][nt], afr[ks][1][0], afr[ks][1][1],
                                  afr[ks][1][2], afr[ks][1][3], b0, b1);
            }
        }
        __syncthreads();   // swsq ready

        // ---- phase 4: dist = min_n(acc + wsq[n]); smem atomic min ----
        float wq[8][2];
        #pragma unroll
        for (int nt = 0; nt < 8; ++nt) {
            wq[nt][0] = swsq[nt * 8 + r * 2    ];
            wq[nt][1] = swsq[nt * 8 + r * 2 + 1];
        }
        float rmin[2][2];
        #pragma unroll
        for (int mt = 0; mt < 2; ++mt)
            #pragma unroll
            for (int h = 0; h < 2; ++h) {
                float m = INF_F;
                #pragma unroll
                for (int nt = 0; nt < 8; ++nt) {
                    m = fminf(m, acc[mt][nt][h * 2    ] + wq[nt][0]);
                    m = fminf(m, acc[mt][nt][h * 2 + 1] + wq[nt][1]);
                }
                rmin[mt][h] = m;
            }
        #pragma unroll
        for (int mt = 0; mt < 2; ++mt)
            #pragma unroll
            for (int h = 0; h < 2; ++h) {
                float v = rmin[mt][h];
                v = fminf(v, __shfl_xor_sync(0xffffffffu, v, 1));
                v = fminf(v, __shfl_xor_sync(0xffffffffu, v, 2));
                rmin[mt][h] = v;
            }
        if (r == 0) {
            #pragma unroll
            for (int mt = 0; mt < 2; ++mt)
                #pragma unroll
                for (int h = 0; h < 2; ++h) {
                    const int row = mbase + mt * 16 + h * 8 + q;
                    const float v = rmin[mt][h] + sssq[row];
                    atomicMin(&sdmin[row], __float_as_int(v));
                }
        }
        __syncthreads();

        // ---- phase 5: fold into global; reset own slot (tid < 128 = all) ----
        {
            const int v = sdmin[tid];
            atomicMin(reinterpret_cast<int*>(out_dist) + b * S_ + tid, v);
            sdmin[tid] = 0x7F800000;
        }
    }
}

// ---------------------------------------------------------------------------
// Kernel 2: fused MLP — coalesced (warp-cooperative dot products), R7 form
// ---------------------------------------------------------------------------
__global__ __launch_bounds__(512) void mlp_kernel(
    const float* __restrict__ dist,
    const float* __restrict__ W1,
    const float* __restrict__ b1,
    const float* __restrict__ W2,
    const float* __restrict__ b2,
    float* __restrict__ out_cls)
{
    __shared__ __align__(16) float4 ds4[S_ / 4];
    __shared__ __align__(16) float  hs[H_];
    const int b    = blockIdx.x;
    const int tid  = threadIdx.x;    // 512 threads = 16 warps
    const int warp = tid >> 5;
    const int lane = tid & 31;

    if (tid < S_ / 4)
        ds4[tid] = reinterpret_cast<const float4*>(dist + b * S_)[tid];
    __syncthreads();

    // Layer 1: warp w computes neurons [w*32, w*32+32)
    {
        const float4 d4 = ds4[lane];
        #pragma unroll
        for (int i = 0; i < 32; ++i) {
            const int h = warp * 32 + i;
            const float4 w4 =
                reinterpret_cast<const float4*>(W1 + h * S_)[lane];
            float acc = d4.x * w4.x;
            acc = fmaf(d4.y, w4.y, acc);
            acc = fmaf(d4.z, w4.z, acc);
            acc = fmaf(d4.w, w4.w, acc);
            #pragma unroll
            for (int off = 16; off > 0; off >>= 1)
                acc += __shfl_xor_sync(0xffffffffu, acc, off);
            if (lane == 0) hs[h] = fmaxf(acc + b1[h], 0.f);
        }
    }
    __syncthreads();

    // Layer 2: warp w (< 10) computes class w
    if (warp < C_) {
        const float4* w4p = reinterpret_cast<const float4*>(W2 + warp * H_);
        const float4* h4p = reinterpret_cast<const float4*>(hs);
        float acc = 0.f;
        #pragma unroll
        for (int j = 0; j < H_ / (32 * 4); ++j) {
            const float4 w4 = w4p[lane + j * 32];
            const float4 h4 = h4p[lane + j * 32];
            acc = fmaf(w4.x, h4.x, acc);
            acc = fmaf(w4.y, h4.y, acc);
            acc = fmaf(w4.z, h4.z, acc);
            acc = fmaf(w4.w, h4.w, acc);
        }
        #pragma unroll
        for (int off = 16; off > 0; off >>= 1)
            acc += __shfl_xor_sync(0xffffffffu, acc, off);
        if (lane == 0) out_cls[b * C_ + warp] = acc + b2[warp];
    }
}

// ---------------------------------------------------------------------------
extern "C" void kernel_launch(void* const* d_in, const int* in_sizes, int n_in,
                              void* d_out, int out_size)
{
    const float* x  = (const float*)d_in[0];
    const float* sh = (const float*)d_in[1];
    const float* W1 = (const float*)d_in[2];
    const float* b1 = (const float*)d_in[3];
    const float* W2 = (const float*)d_in[4];
    const float* b2 = (const float*)d_in[5];

    float* out_dist = (float*)d_out;
    float* out_cls  = (float*)d_out + B_ * S_;

    // init distances to a huge positive sentinel (0x7f7f7f7f ~ 3.39e38)
    cudaMemsetAsync(out_dist, 0x7f, B_ * S_ * sizeof(float), 0);

    dist_kernel<<<GRID, THR>>>(x, sh, out_dist);
    mlp_kernel<<<B_, 512>>>(out_dist, W1, b1, W2, b2, out_cls);
}